// round 11
// baseline (speedup 1.0000x reference)
#include <cuda_runtime.h>
#include <cstdint>

#define N_NODES 100000
#define N_EDGES 1000000
#define DIM 64
#define BN_EPS 1e-5f
#define CAP 96                                          // max in-degree bucket

#define GEMM_BM 128                                     // nodes per block
#define GEMM_NBLK ((N_NODES + GEMM_BM - 1) / GEMM_BM)   // 782

// ---------------- scratch (static device globals; BSS -> zero at load) ------
__device__ int   g_cnt[N_NODES];                 // in-degree counters
__device__ int   g_bucket[(size_t)N_NODES * CAP];// per-dst neighbor lists
__device__ float g_aggr[(size_t)N_NODES * DIM];  // mean-aggregated features
__device__ float g_out[(size_t)N_NODES * DIM];   // post-linear output
__device__ float g_bnstats[2 * DIM];             // [0:64) sum, [64:128) sumsq

// ---------------- kernel 1: fused histogram + bucket scatter (2 edges/thr) --
__global__ void k_scatter(const int* __restrict__ ei) {
    int t = blockIdx.x * blockDim.x + threadIdx.x;
    if (blockIdx.x == 0 && threadIdx.x < 2 * DIM) g_bnstats[threadIdx.x] = 0.0f;
    int e = t * 2;
    if (e + 1 < N_EDGES) {
        int2 s = *reinterpret_cast<const int2*>(ei + e);
        int2 d = *reinterpret_cast<const int2*>(ei + N_EDGES + e);
        int p0 = atomicAdd(&g_cnt[d.x], 1);
        if (p0 < CAP) g_bucket[(size_t)d.x * CAP + p0] = s.x;
        int p1 = atomicAdd(&g_cnt[d.y], 1);
        if (p1 < CAP) g_bucket[(size_t)d.y * CAP + p1] = s.y;
    } else if (e < N_EDGES) {
        int src = ei[e];
        int dst = ei[N_EDGES + e];
        int pos = atomicAdd(&g_cnt[dst], 1);
        if (pos < CAP) g_bucket[(size_t)dst * CAP + pos] = src;
    }
}

// ---------------- kernel 2: dst-major aggregation (MLP=8) -------------------
// 16 lanes per node, each lane owns one float4 (4 channels). Indices come
// from the node's contiguous bucket row via 16B vector loads.
__global__ void k_aggr(const float4* __restrict__ x4) {
    int g    = blockIdx.x * (blockDim.x >> 4) + (threadIdx.x >> 4);
    int lane = threadIdx.x & 15;
    if (g >= N_NODES) return;
    int cnt = __ldg(g_cnt + g);
    if (cnt > CAP) cnt = CAP;                        // safety clamp
    const int* bp = g_bucket + (size_t)g * CAP;
    const float4* xl = x4 + lane;
    float4 acc = __ldg(xl + g * (DIM / 4));          // self loop
    float4 acc2 = make_float4(0.f, 0.f, 0.f, 0.f);
    int i = 0;
    for (; i + 8 <= cnt; i += 8) {                   // MLP=8 window
        int4 sa = *reinterpret_cast<const int4*>(bp + i);
        int4 sb = *reinterpret_cast<const int4*>(bp + i + 4);
        float4 v0 = __ldg(xl + sa.x * (DIM / 4));
        float4 v1 = __ldg(xl + sa.y * (DIM / 4));
        float4 v2 = __ldg(xl + sa.z * (DIM / 4));
        float4 v3 = __ldg(xl + sa.w * (DIM / 4));
        float4 v4 = __ldg(xl + sb.x * (DIM / 4));
        float4 v5 = __ldg(xl + sb.y * (DIM / 4));
        float4 v6 = __ldg(xl + sb.z * (DIM / 4));
        float4 v7 = __ldg(xl + sb.w * (DIM / 4));
        acc.x  += (v0.x + v1.x) + (v2.x + v3.x);
        acc.y  += (v0.y + v1.y) + (v2.y + v3.y);
        acc.z  += (v0.z + v1.z) + (v2.z + v3.z);
        acc.w  += (v0.w + v1.w) + (v2.w + v3.w);
        acc2.x += (v4.x + v5.x) + (v6.x + v7.x);
        acc2.y += (v4.y + v5.y) + (v6.y + v7.y);
        acc2.z += (v4.z + v5.z) + (v6.z + v7.z);
        acc2.w += (v4.w + v5.w) + (v6.w + v7.w);
    }
    for (; i + 4 <= cnt; i += 4) {
        int4 s = *reinterpret_cast<const int4*>(bp + i);
        float4 v0 = __ldg(xl + s.x * (DIM / 4));
        float4 v1 = __ldg(xl + s.y * (DIM / 4));
        float4 v2 = __ldg(xl + s.z * (DIM / 4));
        float4 v3 = __ldg(xl + s.w * (DIM / 4));
        acc.x += (v0.x + v1.x) + (v2.x + v3.x);
        acc.y += (v0.y + v1.y) + (v2.y + v3.y);
        acc.z += (v0.z + v1.z) + (v2.z + v3.z);
        acc.w += (v0.w + v1.w) + (v2.w + v3.w);
    }
    for (; i < cnt; i++) {
        float4 v = __ldg(xl + __ldg(bp + i) * (DIM / 4));
        acc.x += v.x; acc.y += v.y; acc.z += v.z; acc.w += v.w;
    }
    acc.x += acc2.x; acc.y += acc2.y; acc.z += acc2.z; acc.w += acc2.w;
    float inv = 1.0f / (float)(cnt + 1);
    acc.x *= inv; acc.y *= inv; acc.z *= inv; acc.w *= inv;
    reinterpret_cast<float4*>(g_aggr)[g * (DIM / 4) + lane] = acc;
}

// ---------------- kernel 3: register-tiled GEMM + BN partial sums -----------
__global__ void __launch_bounds__(256) k_gemm(const float* __restrict__ w,
                                              const float* __restrict__ b) {
    __shared__ float sA[GEMM_BM * DIM];   // sA[n_local*64 + k]
    __shared__ float sW[DIM * DIM];       // sW[k*64 + j] = w[j*64 + k]

    int tid = threadIdx.x;
    int tx = tid & 15;          // channel quad
    int ty = tid >> 4;          // node octet
    int n0 = blockIdx.x * GEMM_BM;

    for (int idx = tid; idx < DIM * DIM; idx += 256) {
        int j = idx >> 6, k = idx & 63;
        sW[k * DIM + j] = w[idx];
    }
    for (int idx = tid; idx < GEMM_BM * (DIM / 4); idx += 256) {
        int row = idx >> 4, q = idx & 15;
        int n = n0 + row;
        float4 v = (n < N_NODES)
            ? reinterpret_cast<const float4*>(g_aggr)[n * (DIM / 4) + q]
            : make_float4(0.f, 0.f, 0.f, 0.f);
        *reinterpret_cast<float4*>(&sA[row * DIM + q * 4]) = v;
    }
    __syncthreads();

    float acc[8][4];
    #pragma unroll
    for (int i = 0; i < 8; i++)
        #pragma unroll
        for (int c = 0; c < 4; c++) acc[i][c] = 0.0f;

    #pragma unroll 4
    for (int k = 0; k < DIM; k++) {
        float4 wv = *reinterpret_cast<const float4*>(&sW[k * DIM + tx * 4]);
        float a[8];
        #pragma unroll
        for (int i = 0; i < 8; i++) a[i] = sA[(ty * 8 + i) * DIM + k];
        #pragma unroll
        for (int i = 0; i < 8; i++) {
            acc[i][0] = fmaf(a[i], wv.x, acc[i][0]);
            acc[i][1] = fmaf(a[i], wv.y, acc[i][1]);
            acc[i][2] = fmaf(a[i], wv.z, acc[i][2]);
            acc[i][3] = fmaf(a[i], wv.w, acc[i][3]);
        }
    }

    float4 bv = *reinterpret_cast<const float4*>(&b[tx * 4]);
    float psum[4] = {0, 0, 0, 0};
    float psq[4]  = {0, 0, 0, 0};

    #pragma unroll
    for (int i = 0; i < 8; i++) {
        int n = n0 + ty * 8 + i;
        if (n < N_NODES) {
            float4 o;
            o.x = acc[i][0] + bv.x;
            o.y = acc[i][1] + bv.y;
            o.z = acc[i][2] + bv.z;
            o.w = acc[i][3] + bv.w;
            reinterpret_cast<float4*>(g_out)[n * (DIM / 4) + tx] = o;
            psum[0] += o.x; psum[1] += o.y; psum[2] += o.z; psum[3] += o.w;
            psq[0] += o.x * o.x; psq[1] += o.y * o.y;
            psq[2] += o.z * o.z; psq[3] += o.w * o.w;
        }
    }

    __syncthreads();
    float (*sRed)[DIM] = reinterpret_cast<float (*)[DIM]>(sA);

    #pragma unroll
    for (int c = 0; c < 4; c++) sRed[ty][tx * 4 + c] = psum[c];
    __syncthreads();
    #pragma unroll
    for (int st = 8; st > 0; st >>= 1) {
        if (ty < st)
            #pragma unroll
            for (int c = 0; c < 4; c++)
                sRed[ty][tx * 4 + c] += sRed[ty + st][tx * 4 + c];
        __syncthreads();
    }
    if (ty == 0)
        #pragma unroll
        for (int c = 0; c < 4; c++)
            atomicAdd(&g_bnstats[tx * 4 + c], sRed[0][tx * 4 + c]);
    __syncthreads();

    #pragma unroll
    for (int c = 0; c < 4; c++) sRed[ty][tx * 4 + c] = psq[c];
    __syncthreads();
    #pragma unroll
    for (int st = 8; st > 0; st >>= 1) {
        if (ty < st)
            #pragma unroll
            for (int c = 0; c < 4; c++)
                sRed[ty][tx * 4 + c] += sRed[ty + st][tx * 4 + c];
        __syncthreads();
    }
    if (ty == 0)
        #pragma unroll
        for (int c = 0; c < 4; c++)
            atomicAdd(&g_bnstats[DIM + tx * 4 + c], sRed[0][tx * 4 + c]);
}

// ---------------- kernel 4: BN finalize + scale/shift + residual + relu -----
// Scale/shift computed once per block (64 threads) into smem, then pure
// streaming. Final store via __stcs (never re-read). Also re-zeroes g_cnt.
__global__ void k_final(const float4* __restrict__ x4,
                        const float* __restrict__ gamma,
                        const float* __restrict__ beta,
                        float4* __restrict__ out4) {
    __shared__ float ssc[DIM], ssh[DIM];
    int tid = threadIdx.x;
    if (tid < DIM) {
        const float invN = 1.0f / (float)N_NODES;
        float s  = g_bnstats[tid];
        float sq = g_bnstats[DIM + tid];
        float m  = s * invN;
        float sc = __ldg(gamma + tid) * rsqrtf(sq * invN - m * m + BN_EPS);
        ssc[tid] = sc;
        ssh[tid] = __ldg(beta + tid) - m * sc;
    }
    __syncthreads();

    int i = blockIdx.x * blockDim.x + tid;
    if (i < N_NODES) g_cnt[i] = 0;                   // reset for next launch
    if (i >= N_NODES * (DIM / 4)) return;
    int q = i & 15;

    float4 sc = *reinterpret_cast<const float4*>(&ssc[q * 4]);
    float4 sh = *reinterpret_cast<const float4*>(&ssh[q * 4]);
    float4 o  = reinterpret_cast<const float4*>(g_out)[i];
    float4 xv = x4[i];
    float4 r;
    r.x = fmaxf(fmaf(o.x, sc.x, sh.x) + xv.x, 0.0f);
    r.y = fmaxf(fmaf(o.y, sc.y, sh.y) + xv.y, 0.0f);
    r.z = fmaxf(fmaf(o.z, sc.z, sh.z) + xv.z, 0.0f);
    r.w = fmaxf(fmaf(o.w, sc.w, sh.w) + xv.w, 0.0f);
    __stcs(out4 + i, r);
}

// ---------------- launch -----------------------------------------------------
extern "C" void kernel_launch(void* const* d_in, const int* in_sizes, int n_in,
                              void* d_out, int out_size) {
    const float* x     = (const float*)d_in[0];
    const int*   ei    = (const int*)d_in[1];
    const float* w     = (const float*)d_in[2];
    const float* b     = (const float*)d_in[3];
    const float* gamma = (const float*)d_in[4];
    const float* beta  = (const float*)d_in[5];
    float*       out   = (float*)d_out;

    const int vec = N_NODES * (DIM / 4);

    k_scatter<<<(N_EDGES / 2 + 255) / 256, 256>>>(ei);
    k_aggr<<<(N_NODES * 16 + 255) / 256, 256>>>((const float4*)x);
    k_gemm<<<GEMM_NBLK, 256>>>(w, b);
    k_final<<<(vec + 255) / 256, 256>>>((const float4*)x, gamma, beta,
                                        (float4*)out);
}

// round 12
// speedup vs baseline: 1.0835x; 1.0835x over previous
#include <cuda_runtime.h>
#include <cstdint>

#define N_NODES 100000
#define N_EDGES 1000000
#define DIM 64
#define BN_EPS 1e-5f
#define CAP 96                                          // max in-degree bucket

#define GEMM_BM 128                                     // nodes per block
#define GEMM_NBLK ((N_NODES + GEMM_BM - 1) / GEMM_BM)   // 782

typedef unsigned long long u64;

// packed fp32x2 FMA (sm_103a): d = a*b + c on both 32-bit halves
#define FMA2(d, a, b, c) \
    asm("fma.rn.f32x2 %0, %1, %2, %3;" : "=l"(d) : "l"(a), "l"(b), "l"(c))
#define PACK_DUP(d, s) \
    asm("mov.b64 %0, {%1, %1};" : "=l"(d) : "r"(s))
#define UNPACK2(lo, hi, in) \
    asm("mov.b64 {%0, %1}, %2;" : "=r"(lo), "=r"(hi) : "l"(in))

// ---------------- scratch (static device globals; BSS -> zero at load) ------
__device__ int   g_cnt[N_NODES];                 // in-degree counters
__device__ int   g_bucket[(size_t)N_NODES * CAP];// per-dst neighbor lists
__device__ float g_aggr[(size_t)N_NODES * DIM];  // mean-aggregated features
__device__ float g_out[(size_t)N_NODES * DIM];   // post-linear output
__device__ float g_bnstats[2 * DIM];             // [0:64) sum, [64:128) sumsq

// ---------------- kernel 1: fused histogram + bucket scatter ----------------
__global__ void k_scatter(const int* __restrict__ ei) {
    int e = blockIdx.x * blockDim.x + threadIdx.x;
    if (blockIdx.x == 0 && threadIdx.x < 2 * DIM) g_bnstats[threadIdx.x] = 0.0f;
    if (e >= N_EDGES) return;
    int src = ei[e];
    int dst = ei[N_EDGES + e];
    int pos = atomicAdd(&g_cnt[dst], 1);
    if (pos < CAP) g_bucket[(size_t)dst * CAP + pos] = src;
}

// ---------------- kernel 2: dst-major aggregation (int4 idx, MLP=4) ---------
__global__ void k_aggr(const float4* __restrict__ x4) {
    int g    = blockIdx.x * (blockDim.x >> 4) + (threadIdx.x >> 4);
    int lane = threadIdx.x & 15;
    if (g >= N_NODES) return;
    int cnt = __ldg(g_cnt + g);
    if (cnt > CAP) cnt = CAP;                        // safety clamp
    const int* bp = g_bucket + (size_t)g * CAP;
    const float4* xl = x4 + lane;
    float4 acc = __ldg(xl + g * (DIM / 4));          // self loop
    int i = 0;
    for (; i + 4 <= cnt; i += 4) {
        int4 s = *reinterpret_cast<const int4*>(bp + i);   // 1 LDG.128 = 4 idx
        float4 v0 = __ldg(xl + s.x * (DIM / 4));
        float4 v1 = __ldg(xl + s.y * (DIM / 4));
        float4 v2 = __ldg(xl + s.z * (DIM / 4));
        float4 v3 = __ldg(xl + s.w * (DIM / 4));
        acc.x += (v0.x + v1.x) + (v2.x + v3.x);
        acc.y += (v0.y + v1.y) + (v2.y + v3.y);
        acc.z += (v0.z + v1.z) + (v2.z + v3.z);
        acc.w += (v0.w + v1.w) + (v2.w + v3.w);
    }
    for (; i < cnt; i++) {
        float4 v = __ldg(xl + __ldg(bp + i) * (DIM / 4));
        acc.x += v.x; acc.y += v.y; acc.z += v.z; acc.w += v.w;
    }
    float inv = 1.0f / (float)(cnt + 1);
    acc.x *= inv; acc.y *= inv; acc.z *= inv; acc.w *= inv;
    reinterpret_cast<float4*>(g_aggr)[g * (DIM / 4) + lane] = acc;
}

// ---------------- kernel 3: register-tiled GEMM (f32x2 FMA) + BN partials ---
// Inner loop uses packed fma.rn.f32x2: channel pairs (j,j+1) come pre-packed
// from sW via a double2 LDS.128 (adjacent floats); the A value is duplicated
// into both halves with one mov.b64 (alu pipe, overlaps FMA pipe).
__global__ void __launch_bounds__(256) k_gemm(const float* __restrict__ w,
                                              const float* __restrict__ b) {
    __shared__ float sA[GEMM_BM * DIM];   // sA[n_local*64 + k]
    __shared__ float sW[DIM * DIM];       // sW[k*64 + j] = w[j*64 + k]

    int tid = threadIdx.x;
    int tx = tid & 15;          // channel quad
    int ty = tid >> 4;          // node octet
    int n0 = blockIdx.x * GEMM_BM;

    for (int idx = tid; idx < DIM * DIM; idx += 256) {
        int j = idx >> 6, k = idx & 63;
        sW[k * DIM + j] = w[idx];
    }
    for (int idx = tid; idx < GEMM_BM * (DIM / 4); idx += 256) {
        int row = idx >> 4, q = idx & 15;
        int n = n0 + row;
        float4 v = (n < N_NODES)
            ? reinterpret_cast<const float4*>(g_aggr)[n * (DIM / 4) + q]
            : make_float4(0.f, 0.f, 0.f, 0.f);
        *reinterpret_cast<float4*>(&sA[row * DIM + q * 4]) = v;
    }
    __syncthreads();

    u64 acc01[8], acc23[8];
    #pragma unroll
    for (int i = 0; i < 8; i++) { acc01[i] = 0ULL; acc23[i] = 0ULL; }

    #pragma unroll 4
    for (int k = 0; k < DIM; k++) {
        // packed weight pairs: (w[k][tx*4+0], +1) and (+2, +3)
        double2 wp = *reinterpret_cast<const double2*>(&sW[k * DIM + tx * 4]);
        u64 w01 = __double_as_longlong(wp.x);
        u64 w23 = __double_as_longlong(wp.y);
        #pragma unroll
        for (int i = 0; i < 8; i++) {
            unsigned a = *reinterpret_cast<const unsigned*>(
                &sA[(ty * 8 + i) * DIM + k]);
            u64 aa; PACK_DUP(aa, a);
            FMA2(acc01[i], aa, w01, acc01[i]);
            FMA2(acc23[i], aa, w23, acc23[i]);
        }
    }

    float4 bv = *reinterpret_cast<const float4*>(&b[tx * 4]);
    float psum[4] = {0, 0, 0, 0};
    float psq[4]  = {0, 0, 0, 0};

    #pragma unroll
    for (int i = 0; i < 8; i++) {
        int n = n0 + ty * 8 + i;
        if (n < N_NODES) {
            unsigned r0, r1, r2, r3;
            UNPACK2(r0, r1, acc01[i]);
            UNPACK2(r2, r3, acc23[i]);
            float4 o;
            o.x = __uint_as_float(r0) + bv.x;
            o.y = __uint_as_float(r1) + bv.y;
            o.z = __uint_as_float(r2) + bv.z;
            o.w = __uint_as_float(r3) + bv.w;
            reinterpret_cast<float4*>(g_out)[n * (DIM / 4) + tx] = o;
            psum[0] += o.x; psum[1] += o.y; psum[2] += o.z; psum[3] += o.w;
            psq[0] += o.x * o.x; psq[1] += o.y * o.y;
            psq[2] += o.z * o.z; psq[3] += o.w * o.w;
        }
    }

    __syncthreads();
    float (*sRed)[DIM] = reinterpret_cast<float (*)[DIM]>(sA);

    #pragma unroll
    for (int c = 0; c < 4; c++) sRed[ty][tx * 4 + c] = psum[c];
    __syncthreads();
    #pragma unroll
    for (int st = 8; st > 0; st >>= 1) {
        if (ty < st)
            #pragma unroll
            for (int c = 0; c < 4; c++)
                sRed[ty][tx * 4 + c] += sRed[ty + st][tx * 4 + c];
        __syncthreads();
    }
    if (ty == 0)
        #pragma unroll
        for (int c = 0; c < 4; c++)
            atomicAdd(&g_bnstats[tx * 4 + c], sRed[0][tx * 4 + c]);
    __syncthreads();

    #pragma unroll
    for (int c = 0; c < 4; c++) sRed[ty][tx * 4 + c] = psq[c];
    __syncthreads();
    #pragma unroll
    for (int st = 8; st > 0; st >>= 1) {
        if (ty < st)
            #pragma unroll
            for (int c = 0; c < 4; c++)
                sRed[ty][tx * 4 + c] += sRed[ty + st][tx * 4 + c];
        __syncthreads();
    }
    if (ty == 0)
        #pragma unroll
        for (int c = 0; c < 4; c++)
            atomicAdd(&g_bnstats[DIM + tx * 4 + c], sRed[0][tx * 4 + c]);
}

// ---------------- kernel 4: BN finalize + scale/shift + residual + relu -----
__global__ void k_final(const float4* __restrict__ x4,
                        const float4* __restrict__ gamma4,
                        const float4* __restrict__ beta4,
                        float4* __restrict__ out4) {
    int i = blockIdx.x * blockDim.x + threadIdx.x;
    if (i < N_NODES) g_cnt[i] = 0;                   // reset for next launch
    if (i >= N_NODES * (DIM / 4)) return;
    int q = i & 15;
    const float invN = 1.0f / (float)N_NODES;

    float4 s  = *reinterpret_cast<const float4*>(&g_bnstats[q * 4]);
    float4 sq = *reinterpret_cast<const float4*>(&g_bnstats[DIM + q * 4]);
    float4 gm = __ldg(gamma4 + q);
    float4 bt = __ldg(beta4 + q);

    float m0 = s.x * invN, m1 = s.y * invN, m2 = s.z * invN, m3 = s.w * invN;
    float sc0 = gm.x * rsqrtf(sq.x * invN - m0 * m0 + BN_EPS);
    float sc1 = gm.y * rsqrtf(sq.y * invN - m1 * m1 + BN_EPS);
    float sc2 = gm.z * rsqrtf(sq.z * invN - m2 * m2 + BN_EPS);
    float sc3 = gm.w * rsqrtf(sq.w * invN - m3 * m3 + BN_EPS);
    float sh0 = bt.x - m0 * sc0;
    float sh1 = bt.y - m1 * sc1;
    float sh2 = bt.z - m2 * sc2;
    float sh3 = bt.w - m3 * sc3;

    float4 o  = reinterpret_cast<const float4*>(g_out)[i];
    float4 xv = x4[i];
    float4 r;
    r.x = fmaxf(fmaf(o.x, sc0, sh0) + xv.x, 0.0f);
    r.y = fmaxf(fmaf(o.y, sc1, sh1) + xv.y, 0.0f);
    r.z = fmaxf(fmaf(o.z, sc2, sh2) + xv.z, 0.0f);
    r.w = fmaxf(fmaf(o.w, sc3, sh3) + xv.w, 0.0f);
    out4[i] = r;
}

// ---------------- launch -----------------------------------------------------
extern "C" void kernel_launch(void* const* d_in, const int* in_sizes, int n_in,
                              void* d_out, int out_size) {
    const float* x     = (const float*)d_in[0];
    const int*   ei    = (const int*)d_in[1];
    const float* w     = (const float*)d_in[2];
    const float* b     = (const float*)d_in[3];
    const float* gamma = (const float*)d_in[4];
    const float* beta  = (const float*)d_in[5];
    float*       out   = (float*)d_out;

    const int vec = N_NODES * (DIM / 4);

    k_scatter<<<(N_EDGES + 255) / 256, 256>>>(ei);
    k_aggr<<<(N_NODES * 16 + 255) / 256, 256>>>((const float4*)x);
    k_gemm<<<GEMM_NBLK, 256>>>(w, b);
    k_final<<<(vec + 255) / 256, 256>>>((const float4*)x,
                                        (const float4*)gamma,
                                        (const float4*)beta,
                                        (float4*)out);
}